// round 8
// baseline (speedup 1.0000x reference)
#include <cuda_runtime.h>
#include <cuda_bf16.h>
#include <mma.h>
#include <cstdint>
#include <math.h>

using namespace nvcuda;

#define NN 50000
#define CC 128
#define EE 800000
#define NPAD 50048            // 391 * 128
#define RTILES 391            // NPAD / 128
#define AGG_PER_BLK 43        // ceil(50000 / 1173)

// ---------------- scratch (static device globals; no allocation) ----------
__device__ float g_sA[NN * CC];
__device__ float g_sB[NN * CC];
__device__ float g_gi[NPAD * 3 * CC];
__device__ float g_gh[NPAD * 3 * CC];
__device__ float g_wcomb[384 * CC];
__device__ int   g_cnt[NN];
__device__ int   g_rowptr[NN + 1];
__device__ int   g_perm[EE];
__device__ int   g_bsum[64];

__device__ __nv_bfloat16 g_sxh[NPAD * CC];
__device__ __nv_bfloat16 g_sxl[NPAD * CC];
__device__ __nv_bfloat16 g_sph[NPAD * CC];
__device__ __nv_bfloat16 g_spl[NPAD * CC];
__device__ __nv_bfloat16 g_wch[384 * CC];
__device__ __nv_bfloat16 g_wcl[384 * CC];
__device__ __nv_bfloat16 g_whhh[384 * CC];
__device__ __nv_bfloat16 g_whhl[384 * CC];

// ---------------- small utility kernels -----------------------------------
__global__ void zero_int(int* p, int n) {
    int i = blockIdx.x * blockDim.x + threadIdx.x;
    if (i < n) p[i] = 0;
}

__global__ void zero_pad_bf16(__nv_bfloat16* a, __nv_bfloat16* b,
                              __nv_bfloat16* c, __nv_bfloat16* d) {
    int i = blockIdx.x * blockDim.x + threadIdx.x;
    int n = (NPAD - NN) * CC;
    if (i < n) {
        int off = NN * CC + i;
        __nv_bfloat16 z = __float2bfloat16(0.f);
        a[off] = z; b[off] = z; c[off] = z; d[off] = z;
    }
}

__global__ void count_k(const int* __restrict__ dst, int* __restrict__ cnt) {
    int e = blockIdx.x * blockDim.x + threadIdx.x;
    if (e < EE) {
        int d = dst[e];
        d = min(max(d, 0), NN - 1);
        atomicAdd(&cnt[d], 1);
    }
}

__global__ void scan_block(const int* __restrict__ cnt, int* __restrict__ excl,
                           int* __restrict__ bsum, int n) {
    __shared__ int sm[1024];
    int t = threadIdx.x;
    int g = blockIdx.x * 1024 + t;
    int v = (g < n) ? cnt[g] : 0;
    sm[t] = v;
    __syncthreads();
    for (int off = 1; off < 1024; off <<= 1) {
        int tv = 0;
        if (t >= off) tv = sm[t - off];
        __syncthreads();
        if (t >= off) sm[t] += tv;
        __syncthreads();
    }
    if (g < n) excl[g] = sm[t] - v;
    if (t == 1023) bsum[blockIdx.x] = sm[1023];
}

__global__ void scan_sums(int* bsum, int nb) {
    int run = 0;
    for (int i = 0; i < nb; i++) { int t = bsum[i]; bsum[i] = run; run += t; }
}

__global__ void add_off(int* __restrict__ rowptr, const int* __restrict__ bsum, int n) {
    int g = blockIdx.x * blockDim.x + threadIdx.x;
    if (g < n) rowptr[g] += bsum[g >> 10];
    if (g == 0) rowptr[n] = EE;
}

__global__ void fill_k(const int* __restrict__ src, const int* __restrict__ dst,
                       const int* __restrict__ rowptr, int* __restrict__ cur,
                       int* __restrict__ perm) {
    int e = blockIdx.x * blockDim.x + threadIdx.x;
    if (e < EE) {
        int d = dst[e];
        d = min(max(d, 0), NN - 1);
        int s = src[e];
        s = min(max(s, 0), NN - 1);
        int pos = rowptr[d] + atomicAdd(&cur[d], 1);
        if (pos >= 0 && pos < EE) perm[pos] = s;
    }
}

// ---------------- W_comb = W_ih @ W_lin (fp32, once) -----------------------
__global__ void wcomb_k(const float* __restrict__ W_ih, const float* __restrict__ W_lin,
                        float* __restrict__ W_comb) {
    int i = blockIdx.x;
    int j = threadIdx.x;
    float s = 0.f;
    #pragma unroll 8
    for (int k = 0; k < 128; k++)
        s += W_ih[i * 128 + k] * W_lin[k * 128 + j];
    W_comb[i * 128 + j] = s;
}

// ---------------- fp32 -> bf16 hi/lo split ---------------------------------
__global__ void conv_split(const float* __restrict__ x, __nv_bfloat16* __restrict__ hi,
                           __nv_bfloat16* __restrict__ lo, int n4) {
    int i = blockIdx.x * blockDim.x + threadIdx.x;
    if (i >= n4) return;
    float4 v = ((const float4*)x)[i];
    __nv_bfloat16 h0 = __float2bfloat16(v.x);
    __nv_bfloat16 h1 = __float2bfloat16(v.y);
    __nv_bfloat16 h2 = __float2bfloat16(v.z);
    __nv_bfloat16 h3 = __float2bfloat16(v.w);
    __nv_bfloat16 l0 = __float2bfloat16(v.x - __bfloat162float(h0));
    __nv_bfloat16 l1 = __float2bfloat16(v.y - __bfloat162float(h1));
    __nv_bfloat16 l2 = __float2bfloat16(v.z - __bfloat162float(h2));
    __nv_bfloat16 l3 = __float2bfloat16(v.w - __bfloat162float(h3));
    __nv_bfloat162* hp = (__nv_bfloat162*)hi;
    __nv_bfloat162* lp = (__nv_bfloat162*)lo;
    hp[i * 2 + 0] = __nv_bfloat162(h0, h1);
    hp[i * 2 + 1] = __nv_bfloat162(h2, h3);
    lp[i * 2 + 0] = __nv_bfloat162(l0, l1);
    lp[i * 2 + 1] = __nv_bfloat162(l2, l3);
}

// ---------------- shared GEMM tile body (term-major MMA ordering) ----------
// Y[128,128]@(row0,col0) += (Ah+Al)@(Bh+Bl)^T, drop Al*Bl. 256 threads.
// Uses named barrier 1 with 256 arrivals so it can live inside a 384-thread
// warp-specialized block.
#define LDSB 136                              // 128 + 8 bf16 pad
#define SM_T (128 * LDSB)                     // one 128x128 bf16 tile
#define GT_SMEM (4 * SM_T * 2)                // 139264 bytes

__device__ __forceinline__ void gemm_tile_body(
    const __nv_bfloat16* __restrict__ Ah, const __nv_bfloat16* __restrict__ Al,
    const __nv_bfloat16* __restrict__ Bh, const __nv_bfloat16* __restrict__ Bl,
    float* __restrict__ Y, int M, int row0, int col0,
    __nv_bfloat16* smb, int t) {
    __nv_bfloat16* As_h = smb;
    __nv_bfloat16* As_l = smb + SM_T;
    __nv_bfloat16* Bs_h = smb + 2 * SM_T;
    __nv_bfloat16* Bs_l = smb + 3 * SM_T;

    {
        const uint4* gAh = (const uint4*)(Ah + (size_t)row0 * 128);
        const uint4* gAl = (const uint4*)(Al + (size_t)row0 * 128);
        const uint4* gBh = (const uint4*)(Bh + (size_t)col0 * 128);
        const uint4* gBl = (const uint4*)(Bl + (size_t)col0 * 128);
        #pragma unroll
        for (int i = 0; i < 8; i++) {
            int idx = t + i * 256;
            int r = idx >> 4;
            int c = idx & 15;
            ((uint4*)(As_h + r * LDSB))[c] = gAh[r * 16 + c];
            ((uint4*)(As_l + r * LDSB))[c] = gAl[r * 16 + c];
            ((uint4*)(Bs_h + r * LDSB))[c] = gBh[r * 16 + c];
            ((uint4*)(Bs_l + r * LDSB))[c] = gBl[r * 16 + c];
        }
    }
    asm volatile("bar.sync 1, 256;" ::: "memory");

    int wid = t >> 5;
    int wm = wid & 3;       // 0..3 -> 32-row slabs
    int wn = wid >> 2;      // 0..1 -> 64-col slabs

    wmma::fragment<wmma::accumulator, 16, 16, 16, float> acc[2][4];
    #pragma unroll
    for (int i = 0; i < 2; i++)
        #pragma unroll
        for (int j = 0; j < 4; j++) wmma::fill_fragment(acc[i][j], 0.0f);

    #pragma unroll
    for (int ks = 0; ks < 8; ks++) {
        int k0 = ks * 16;
        // phase 1: ah x bh (8 independent MMAs)
        wmma::fragment<wmma::matrix_a, 16, 16, 16, __nv_bfloat16, wmma::row_major> ah[2];
        #pragma unroll
        for (int i = 0; i < 2; i++)
            wmma::load_matrix_sync(ah[i], &As_h[(wm * 32 + i * 16) * LDSB + k0], LDSB);
        {
            wmma::fragment<wmma::matrix_b, 16, 16, 16, __nv_bfloat16, wmma::col_major> bh[4];
            #pragma unroll
            for (int j = 0; j < 4; j++)
                wmma::load_matrix_sync(bh[j], &Bs_h[(wn * 64 + j * 16) * LDSB + k0], LDSB);
            #pragma unroll
            for (int i = 0; i < 2; i++)
                #pragma unroll
                for (int j = 0; j < 4; j++)
                    wmma::mma_sync(acc[i][j], ah[i], bh[j], acc[i][j]);
            // phase 2: al x bh (reuse bh; 8 independent MMAs, each 8 issues
            // after its phase-1 dependent predecessor)
            wmma::fragment<wmma::matrix_a, 16, 16, 16, __nv_bfloat16, wmma::row_major> al[2];
            #pragma unroll
            for (int i = 0; i < 2; i++)
                wmma::load_matrix_sync(al[i], &As_l[(wm * 32 + i * 16) * LDSB + k0], LDSB);
            #pragma unroll
            for (int i = 0; i < 2; i++)
                #pragma unroll
                for (int j = 0; j < 4; j++)
                    wmma::mma_sync(acc[i][j], al[i], bh[j], acc[i][j]);
        }
        // phase 3: ah x bl (bh dead; 8 independent MMAs)
        {
            wmma::fragment<wmma::matrix_b, 16, 16, 16, __nv_bfloat16, wmma::col_major> bl[4];
            #pragma unroll
            for (int j = 0; j < 4; j++)
                wmma::load_matrix_sync(bl[j], &Bs_l[(wn * 64 + j * 16) * LDSB + k0], LDSB);
            #pragma unroll
            for (int i = 0; i < 2; i++)
                #pragma unroll
                for (int j = 0; j < 4; j++)
                    wmma::mma_sync(acc[i][j], ah[i], bl[j], acc[i][j]);
        }
    }

    #pragma unroll
    for (int i = 0; i < 2; i++) {
        #pragma unroll
        for (int j = 0; j < 4; j++) {
            size_t off = (size_t)(row0 + wm * 32 + i * 16) * M + col0 + wn * 64 + j * 16;
            wmma::store_matrix_sync(&Y[off], acc[i][j], M, wmma::mem_row_major);
        }
    }
}

// ---------------- standalone GEMM ------------------------------------------
__global__ __launch_bounds__(256, 1)
void gemm_tc(const __nv_bfloat16* __restrict__ Ah, const __nv_bfloat16* __restrict__ Al,
             const __nv_bfloat16* __restrict__ Bh, const __nv_bfloat16* __restrict__ Bl,
             float* __restrict__ Y, int M) {
    extern __shared__ __nv_bfloat16 smb[];
    gemm_tile_body(Ah, Al, Bh, Bl, Y, M,
                   blockIdx.x * 128, blockIdx.y * 128, smb, threadIdx.x);
}

// ---------------- warp-specialized fused: gh GEMM + aggregation -----------
// 384 threads: t<256 -> GEMM (smem/tensor pipes); t>=256 -> CSR aggregate
// (LSU/L2 pipes). Both depend only on state, so they overlap.
__global__ __launch_bounds__(384, 1)
void fused_gh_agg(const __nv_bfloat16* __restrict__ Ah, const __nv_bfloat16* __restrict__ Al,
                  const __nv_bfloat16* __restrict__ Bh, const __nv_bfloat16* __restrict__ Bl,
                  float* __restrict__ Y,
                  const float* __restrict__ st, const int* __restrict__ rowptr,
                  const int* __restrict__ perm,
                  __nv_bfloat16* __restrict__ ph, __nv_bfloat16* __restrict__ pl) {
    extern __shared__ __nv_bfloat16 smb[];
    int t = threadIdx.x;
    if (t < 256) {
        gemm_tile_body(Ah, Al, Bh, Bl, Y, 384,
                       (blockIdx.x % RTILES) * 128, (blockIdx.x / RTILES) * 128,
                       smb, t);
    } else {
        int c = t - 256;                    // 0..127 channel
        int r0 = blockIdx.x * AGG_PER_BLK;
        #pragma unroll 1
        for (int it = 0; it < AGG_PER_BLK; it++) {
            int i = r0 + it;
            if (i >= NN) break;
            int s0 = rowptr[i], s1 = rowptr[i + 1];
            float a0 = 0.f, a1 = 0.f, a2 = 0.f, a3 = 0.f;
            int e = s0;
            for (; e + 3 < s1; e += 4) {
                int p0 = perm[e], p1 = perm[e + 1], p2 = perm[e + 2], p3 = perm[e + 3];
                a0 += st[p0 * 128 + c];
                a1 += st[p1 * 128 + c];
                a2 += st[p2 * 128 + c];
                a3 += st[p3 * 128 + c];
            }
            for (; e < s1; e++) a0 += st[perm[e] * 128 + c];
            float s = (a0 + a1) + (a2 + a3);
            __nv_bfloat16 h = __float2bfloat16(s);
            ph[i * 128 + c] = h;
            pl[i * 128 + c] = __float2bfloat16(s - __bfloat162float(h));
        }
    }
}

// ---------------- standalone aggregation (step 0) ---------------------------
__global__ void aggregate(const float* __restrict__ st, const int* __restrict__ rowptr,
                          const int* __restrict__ perm,
                          __nv_bfloat16* __restrict__ ph, __nv_bfloat16* __restrict__ pl) {
    int i = blockIdx.x;
    int c = threadIdx.x;
    int s0 = rowptr[i], s1 = rowptr[i + 1];
    float a0 = 0.f, a1 = 0.f, a2 = 0.f, a3 = 0.f;
    int e = s0;
    for (; e + 3 < s1; e += 4) {
        int p0 = perm[e], p1 = perm[e + 1], p2 = perm[e + 2], p3 = perm[e + 3];
        a0 += st[p0 * 128 + c];
        a1 += st[p1 * 128 + c];
        a2 += st[p2 * 128 + c];
        a3 += st[p3 * 128 + c];
    }
    for (; e < s1; e++) a0 += st[perm[e] * 128 + c];
    float s = (a0 + a1) + (a2 + a3);
    __nv_bfloat16 h = __float2bfloat16(s);
    ph[i * 128 + c] = h;
    pl[i * 128 + c] = __float2bfloat16(s - __bfloat162float(h));
}

// ---------------- GRU elementwise, float4 vectorized ------------------------
__global__ void gru_k(const float* __restrict__ gi, const float* __restrict__ gh,
                      const float* __restrict__ b_ih, const float* __restrict__ b_hh,
                      const float* __restrict__ h, float* __restrict__ out,
                      __nv_bfloat16* __restrict__ oh, __nv_bfloat16* __restrict__ ol,
                      int n4) {
    int idx = blockIdx.x * blockDim.x + threadIdx.x;
    if (idx >= n4) return;
    int i = idx >> 5;
    int c4 = (idx & 31) * 4;
    const float4* gir = (const float4*)(gi + (size_t)i * 384 + c4);
    const float4* ghr = (const float4*)(gh + (size_t)i * 384 + c4);
    float4 ir = gir[0],  iz = gir[32],  in_ = gir[64];
    float4 hr = ghr[0],  hz = ghr[32],  hn = ghr[64];
    float4 bir = *(const float4*)(b_ih + c4);
    float4 biz = *(const float4*)(b_ih + 128 + c4);
    float4 bin = *(const float4*)(b_ih + 256 + c4);
    float4 bhr = *(const float4*)(b_hh + c4);
    float4 bhz = *(const float4*)(b_hh + 128 + c4);
    float4 bhn = *(const float4*)(b_hh + 256 + c4);
    float4 hv = *(const float4*)(h + (size_t)i * 128 + c4);

    float o[4], ohh[4], oll[4];
    #pragma unroll
    for (int q = 0; q < 4; q++) {
        float irq = ((&ir.x)[q] + (&bir.x)[q]) + ((&hr.x)[q] + (&bhr.x)[q]);
        float izq = ((&iz.x)[q] + (&biz.x)[q]) + ((&hz.x)[q] + (&bhz.x)[q]);
        float inq = (&in_.x)[q] + (&bin.x)[q];
        float hnq = (&hn.x)[q] + (&bhn.x)[q];
        float r = 1.f / (1.f + expf(-irq));
        float z = 1.f / (1.f + expf(-izq));
        float nval = tanhf(inq + r * hnq);
        float val = (1.f - z) * nval + z * (&hv.x)[q];
        o[q] = val;
        __nv_bfloat16 vh = __float2bfloat16(val);
        ohh[q] = __bfloat162float(vh);
        oll[q] = val - ohh[q];
    }
    *(float4*)(out + (size_t)i * 128 + c4) = make_float4(o[0], o[1], o[2], o[3]);
    __nv_bfloat162* ohp = (__nv_bfloat162*)(oh + (size_t)i * 128 + c4);
    __nv_bfloat162* olp = (__nv_bfloat162*)(ol + (size_t)i * 128 + c4);
    ohp[0] = __nv_bfloat162(__float2bfloat16(ohh[0]), __float2bfloat16(ohh[1]));
    ohp[1] = __nv_bfloat162(__float2bfloat16(ohh[2]), __float2bfloat16(ohh[3]));
    olp[0] = __nv_bfloat162(__float2bfloat16(oll[0]), __float2bfloat16(oll[1]));
    olp[1] = __nv_bfloat162(__float2bfloat16(oll[2]), __float2bfloat16(oll[3]));
}

// ---------------- launcher --------------------------------------------------
extern "C" void kernel_launch(void* const* d_in, const int* in_sizes, int n_in,
                              void* d_out, int out_size) {
    const float* x     = (const float*)d_in[0];
    const int*   ei    = (const int*)d_in[1];
    const float* W_lin = (const float*)d_in[2];
    const float* W_ih  = (const float*)d_in[3];
    const float* W_hh  = (const float*)d_in[4];
    const float* b_ih  = (const float*)d_in[5];
    const float* b_hh  = (const float*)d_in[6];
    float* out = (float*)d_out;

    const int* src = ei;
    const int* dst = ei + EE;

    float *sA_, *sB_, *gi_, *gh_, *wc_;
    int *cnt_, *rp_, *perm_, *bsum_;
    __nv_bfloat16 *sxh_, *sxl_, *sph_, *spl_, *wch_, *wcl_, *whhh_, *whhl_;
    cudaGetSymbolAddress((void**)&sA_,   g_sA);
    cudaGetSymbolAddress((void**)&sB_,   g_sB);
    cudaGetSymbolAddress((void**)&gi_,   g_gi);
    cudaGetSymbolAddress((void**)&gh_,   g_gh);
    cudaGetSymbolAddress((void**)&wc_,   g_wcomb);
    cudaGetSymbolAddress((void**)&cnt_,  g_cnt);
    cudaGetSymbolAddress((void**)&rp_,   g_rowptr);
    cudaGetSymbolAddress((void**)&perm_, g_perm);
    cudaGetSymbolAddress((void**)&bsum_, g_bsum);
    cudaGetSymbolAddress((void**)&sxh_,  g_sxh);
    cudaGetSymbolAddress((void**)&sxl_,  g_sxl);
    cudaGetSymbolAddress((void**)&sph_,  g_sph);
    cudaGetSymbolAddress((void**)&spl_,  g_spl);
    cudaGetSymbolAddress((void**)&wch_,  g_wch);
    cudaGetSymbolAddress((void**)&wcl_,  g_wcl);
    cudaGetSymbolAddress((void**)&whhh_, g_whhh);
    cudaGetSymbolAddress((void**)&whhl_, g_whhl);

    cudaFuncSetAttribute(gemm_tc, cudaFuncAttributeMaxDynamicSharedMemorySize, GT_SMEM);
    cudaFuncSetAttribute(fused_gh_agg, cudaFuncAttributeMaxDynamicSharedMemorySize, GT_SMEM);

    const int NB_SCAN = (NN + 1023) / 1024;
    const int N4 = NN * CC / 4;
    const dim3 gg(RTILES, 3);                 // 391 x 3
    const int FB = RTILES * 3;                // 1173 fused blocks

    // launch order: gemm_tc at my #4 (ncu -s 5 -c 1 lands there)
    conv_split<<<(N4 + 255) / 256, 256>>>(x, sxh_, sxl_, N4);                          // 1
    conv_split<<<(384 * CC / 4 + 255) / 256, 256>>>(W_hh, whhh_, whhl_, 384 * CC / 4); // 2
    zero_pad_bf16<<<((NPAD - NN) * CC + 255) / 256, 256>>>(sxh_, sxl_, sph_, spl_);    // 3
    gemm_tc<<<gg, 256, GT_SMEM>>>(sxh_, sxl_, whhh_, whhl_, gh_, 384);                 // 4 (profiled)

    wcomb_k<<<384, 128>>>(W_ih, W_lin, wc_);
    conv_split<<<(384 * CC / 4 + 255) / 256, 256>>>(wc_, wch_, wcl_, 384 * CC / 4);

    // ---- build CSR ----
    zero_int <<<(NN + 255) / 256, 256>>>(cnt_, NN);
    count_k  <<<(EE + 255) / 256, 256>>>(dst, cnt_);
    scan_block<<<NB_SCAN, 1024>>>(cnt_, rp_, bsum_, NN);
    scan_sums <<<1, 1>>>(bsum_, NB_SCAN);
    add_off   <<<(NN + 255) / 256, 256>>>(rp_, bsum_, NN);
    zero_int  <<<(NN + 255) / 256, 256>>>(cnt_, NN);
    fill_k    <<<(EE + 255) / 256, 256>>>(src, dst, rp_, cnt_, perm_);

    // ---- step 0 (gh already computed at launch 4) ----
    aggregate<<<NN, 128>>>(x, rp_, perm_, sph_, spl_);
    gemm_tc<<<gg, 256, GT_SMEM>>>(sph_, spl_, wch_, wcl_, gi_, 384);
    gru_k<<<(N4 + 255) / 256, 256>>>(gi_, gh_, b_ih, b_hh, x, sA_, sxh_, sxl_, N4);

    // ---- steps 1, 2: fused gh-GEMM + aggregation ----
    const float* sin = sA_;
    for (int step = 1; step < 3; step++) {
        float* sout = (step == 2) ? out : sB_;

        fused_gh_agg<<<FB, 384, GT_SMEM>>>(sxh_, sxl_, whhh_, whhl_, gh_,
                                           sin, rp_, perm_, sph_, spl_);
        gemm_tc<<<gg, 256, GT_SMEM>>>(sph_, spl_, wch_, wcl_, gi_, 384);
        gru_k<<<(N4 + 255) / 256, 256>>>(gi_, gh_, b_ih, b_hh, sin, sout,
                                         sxh_, sxl_, N4);
        sin = sout;
    }
}

// round 9
// speedup vs baseline: 2.3096x; 2.3096x over previous
#include <cuda_runtime.h>
#include <cuda_bf16.h>
#include <cstdint>
#include <math.h>

#define NN 50000
#define CC 128
#define EE 800000
#define NPAD 50048            // 391 * 128
#define RTILES 391

// ---------------- scratch (static device globals; no allocation) ----------
__device__ float g_sA[NN * CC];
__device__ float g_sB[NN * CC];
__device__ float g_gi[NPAD * 3 * CC];
__device__ float g_gh[NPAD * 3 * CC];
__device__ float g_wcomb[384 * CC];
__device__ int   g_cnt[NN];
__device__ int   g_rowptr[NN + 1];
__device__ int   g_perm[EE];
__device__ int   g_bsum[64];

__device__ __nv_bfloat16 g_sxh[NPAD * CC];
__device__ __nv_bfloat16 g_sxl[NPAD * CC];
__device__ __nv_bfloat16 g_sph[NPAD * CC];
__device__ __nv_bfloat16 g_spl[NPAD * CC];
__device__ __nv_bfloat16 g_wch[384 * CC];
__device__ __nv_bfloat16 g_wcl[384 * CC];
__device__ __nv_bfloat16 g_whhh[384 * CC];
__device__ __nv_bfloat16 g_whhl[384 * CC];

// ---------------- PTX helpers ----------------------------------------------
__device__ __forceinline__ uint32_t smem_u32(const void* p) {
    uint32_t a;
    asm("{ .reg .u64 t; cvta.to.shared.u64 t, %1; cvt.u32.u64 %0, t; }" : "=r"(a) : "l"(p));
    return a;
}
__device__ __forceinline__ void ldsm4(uint32_t* r, uint32_t addr) {
    asm volatile("ldmatrix.sync.aligned.m8n8.x4.shared.b16 {%0,%1,%2,%3}, [%4];"
                 : "=r"(r[0]), "=r"(r[1]), "=r"(r[2]), "=r"(r[3]) : "r"(addr));
}
__device__ __forceinline__ void mma_bf16(float* d, const uint32_t* a,
                                         uint32_t b0, uint32_t b1) {
    asm volatile(
        "mma.sync.aligned.m16n8k16.row.col.f32.bf16.bf16.f32 "
        "{%0,%1,%2,%3}, {%4,%5,%6,%7}, {%8,%9}, {%0,%1,%2,%3};"
        : "+f"(d[0]), "+f"(d[1]), "+f"(d[2]), "+f"(d[3])
        : "r"(a[0]), "r"(a[1]), "r"(a[2]), "r"(a[3]), "r"(b0), "r"(b1));
}

// ---------------- small utility kernels -----------------------------------
__global__ void zero_int(int* p, int n) {
    int i = blockIdx.x * blockDim.x + threadIdx.x;
    if (i < n) p[i] = 0;
}

__global__ void zero_pad_bf16(__nv_bfloat16* a, __nv_bfloat16* b,
                              __nv_bfloat16* c, __nv_bfloat16* d) {
    int i = blockIdx.x * blockDim.x + threadIdx.x;
    int n = (NPAD - NN) * CC;
    if (i < n) {
        int off = NN * CC + i;
        __nv_bfloat16 z = __float2bfloat16(0.f);
        a[off] = z; b[off] = z; c[off] = z; d[off] = z;
    }
}

__global__ void count_k(const int* __restrict__ dst, int* __restrict__ cnt) {
    int e = blockIdx.x * blockDim.x + threadIdx.x;
    if (e < EE) {
        int d = dst[e];
        d = min(max(d, 0), NN - 1);
        atomicAdd(&cnt[d], 1);
    }
}

__global__ void scan_block(const int* __restrict__ cnt, int* __restrict__ excl,
                           int* __restrict__ bsum, int n) {
    __shared__ int sm[1024];
    int t = threadIdx.x;
    int g = blockIdx.x * 1024 + t;
    int v = (g < n) ? cnt[g] : 0;
    sm[t] = v;
    __syncthreads();
    for (int off = 1; off < 1024; off <<= 1) {
        int tv = 0;
        if (t >= off) tv = sm[t - off];
        __syncthreads();
        if (t >= off) sm[t] += tv;
        __syncthreads();
    }
    if (g < n) excl[g] = sm[t] - v;
    if (t == 1023) bsum[blockIdx.x] = sm[1023];
}

__global__ void scan_sums(int* bsum, int nb) {
    int run = 0;
    for (int i = 0; i < nb; i++) { int t = bsum[i]; bsum[i] = run; run += t; }
}

__global__ void add_off(int* __restrict__ rowptr, const int* __restrict__ bsum, int n) {
    int g = blockIdx.x * blockDim.x + threadIdx.x;
    if (g < n) rowptr[g] += bsum[g >> 10];
    if (g == 0) rowptr[n] = EE;
}

__global__ void fill_k(const int* __restrict__ src, const int* __restrict__ dst,
                       const int* __restrict__ rowptr, int* __restrict__ cur,
                       int* __restrict__ perm) {
    int e = blockIdx.x * blockDim.x + threadIdx.x;
    if (e < EE) {
        int d = dst[e];
        d = min(max(d, 0), NN - 1);
        int s = src[e];
        s = min(max(s, 0), NN - 1);
        int pos = rowptr[d] + atomicAdd(&cur[d], 1);
        if (pos >= 0 && pos < EE) perm[pos] = s;
    }
}

// ---------------- W_comb = W_ih @ W_lin (fp32, once) -----------------------
__global__ void wcomb_k(const float* __restrict__ W_ih, const float* __restrict__ W_lin,
                        float* __restrict__ W_comb) {
    int i = blockIdx.x;
    int j = threadIdx.x;
    float s = 0.f;
    #pragma unroll 8
    for (int k = 0; k < 128; k++)
        s += W_ih[i * 128 + k] * W_lin[k * 128 + j];
    W_comb[i * 128 + j] = s;
}

// ---------------- fp32 -> bf16 hi/lo split ---------------------------------
__global__ void conv_split(const float* __restrict__ x, __nv_bfloat16* __restrict__ hi,
                           __nv_bfloat16* __restrict__ lo, int n4) {
    int i = blockIdx.x * blockDim.x + threadIdx.x;
    if (i >= n4) return;
    float4 v = ((const float4*)x)[i];
    __nv_bfloat16 h0 = __float2bfloat16(v.x);
    __nv_bfloat16 h1 = __float2bfloat16(v.y);
    __nv_bfloat16 h2 = __float2bfloat16(v.z);
    __nv_bfloat16 h3 = __float2bfloat16(v.w);
    __nv_bfloat16 l0 = __float2bfloat16(v.x - __bfloat162float(h0));
    __nv_bfloat16 l1 = __float2bfloat16(v.y - __bfloat162float(h1));
    __nv_bfloat16 l2 = __float2bfloat16(v.z - __bfloat162float(h2));
    __nv_bfloat16 l3 = __float2bfloat16(v.w - __bfloat162float(h3));
    __nv_bfloat162* hp = (__nv_bfloat162*)hi;
    __nv_bfloat162* lp = (__nv_bfloat162*)lo;
    hp[i * 2 + 0] = __nv_bfloat162(h0, h1);
    hp[i * 2 + 1] = __nv_bfloat162(h2, h3);
    lp[i * 2 + 0] = __nv_bfloat162(l0, l1);
    lp[i * 2 + 1] = __nv_bfloat162(l2, l3);
}

// ---------------- hand mma split-bf16 GEMM ---------------------------------
// Y[NPAD, M] = (Ah+Al)[NPAD,128] @ ((Bh+Bl)[M,128])^T, drop Al*Bl.
// block tile 128x64, 256 threads (8 warps, 4x2), warp tile 32x32.
// smem rows padded to 136 bf16 (272 B): row stride mod 128 = 16 -> ldmatrix
// conflict-free. 104448 B smem -> 2 CTAs/SM.
#define LDSB 136
#define ROWB (LDSB * 2)                       // 272 bytes per smem row
#define A_T (128 * LDSB)                      // bf16 elems per A tile
#define B_T (64 * LDSB)
#define GT_SMEM ((2 * A_T + 2 * B_T) * 2)     // 104448 bytes

__global__ __launch_bounds__(256, 2)
void gemm_tc(const __nv_bfloat16* __restrict__ Ah, const __nv_bfloat16* __restrict__ Al,
             const __nv_bfloat16* __restrict__ Bh, const __nv_bfloat16* __restrict__ Bl,
             float* __restrict__ Y, int M) {
    extern __shared__ __nv_bfloat16 smb[];
    __nv_bfloat16* As_h = smb;
    __nv_bfloat16* As_l = smb + A_T;
    __nv_bfloat16* Bs_h = smb + 2 * A_T;
    __nv_bfloat16* Bs_l = smb + 2 * A_T + B_T;

    int row0 = blockIdx.x * 128;
    int col0 = blockIdx.y * 64;
    int t = threadIdx.x;

    // ---- global -> smem (A: 2048 uint4/tile; B: 1024 uint4/tile) ----
    {
        const uint4* gAh = (const uint4*)(Ah + (size_t)row0 * 128);
        const uint4* gAl = (const uint4*)(Al + (size_t)row0 * 128);
        #pragma unroll
        for (int i = 0; i < 8; i++) {
            int idx = t + i * 256;
            int r = idx >> 4, c = idx & 15;
            ((uint4*)((char*)As_h + r * ROWB))[c] = gAh[idx];
            ((uint4*)((char*)As_l + r * ROWB))[c] = gAl[idx];
        }
        const uint4* gBh = (const uint4*)(Bh + (size_t)col0 * 128);
        const uint4* gBl = (const uint4*)(Bl + (size_t)col0 * 128);
        #pragma unroll
        for (int i = 0; i < 4; i++) {
            int idx = t + i * 256;
            int r = idx >> 4, c = idx & 15;
            ((uint4*)((char*)Bs_h + r * ROWB))[c] = gBh[idx];
            ((uint4*)((char*)Bs_l + r * ROWB))[c] = gBl[idx];
        }
    }
    __syncthreads();

    int lane = t & 31;
    int wid = t >> 5;
    int wm = wid & 3;       // 32-row slab
    int wn = wid >> 2;      // 32-col slab

    // ldmatrix lane offset: (lane&15) = matrix row, (lane>>4) = 16B half
    uint32_t laneOff = (uint32_t)((lane & 15) * ROWB + (lane >> 4) * 16);
    uint32_t aH = smem_u32(As_h) + (uint32_t)(wm * 32) * ROWB + laneOff;
    uint32_t aL = aH + A_T * 2;
    uint32_t bH = smem_u32(Bs_h) + (uint32_t)(wn * 32) * ROWB + laneOff;
    uint32_t bL = bH + B_T * 2;

    float acc[2][4][4];
    #pragma unroll
    for (int i = 0; i < 2; i++)
        #pragma unroll
        for (int j = 0; j < 4; j++)
            #pragma unroll
            for (int q = 0; q < 4; q++) acc[i][j][q] = 0.f;

    #pragma unroll
    for (int ks = 0; ks < 8; ks++) {
        uint32_t kb = ks * 32;                 // 16 bf16 = 32 bytes
        uint32_t a0[4], a1[4], p0[4], p1[4];
        ldsm4(a0, aH + kb);                    // A rows wm*32+0..15
        ldsm4(a1, aH + 16 * ROWB + kb);        // A rows +16..31
        ldsm4(p0, bH + kb);                    // B(hi) n 0..15 -> frags j0,j1
        ldsm4(p1, bH + 16 * ROWB + kb);        // B(hi) n 16..31 -> frags j2,j3
        // phase 1: ah x bh
        mma_bf16(acc[0][0], a0, p0[0], p0[2]);
        mma_bf16(acc[0][1], a0, p0[1], p0[3]);
        mma_bf16(acc[0][2], a0, p1[0], p1[2]);
        mma_bf16(acc[0][3], a0, p1[1], p1[3]);
        mma_bf16(acc[1][0], a1, p0[0], p0[2]);
        mma_bf16(acc[1][1], a1, p0[1], p0[3]);
        mma_bf16(acc[1][2], a1, p1[0], p1[2]);
        mma_bf16(acc[1][3], a1, p1[1], p1[3]);
        // phase 2: al x bh
        uint32_t c0[4], c1[4];
        ldsm4(c0, aL + kb);
        ldsm4(c1, aL + 16 * ROWB + kb);
        mma_bf16(acc[0][0], c0, p0[0], p0[2]);
        mma_bf16(acc[0][1], c0, p0[1], p0[3]);
        mma_bf16(acc[0][2], c0, p1[0], p1[2]);
        mma_bf16(acc[0][3], c0, p1[1], p1[3]);
        mma_bf16(acc[1][0], c1, p0[0], p0[2]);
        mma_bf16(acc[1][1], c1, p0[1], p0[3]);
        mma_bf16(acc[1][2], c1, p1[0], p1[2]);
        mma_bf16(acc[1][3], c1, p1[1], p1[3]);
        // phase 3: ah x bl
        uint32_t q0[4], q1[4];
        ldsm4(q0, bL + kb);
        ldsm4(q1, bL + 16 * ROWB + kb);
        mma_bf16(acc[0][0], a0, q0[0], q0[2]);
        mma_bf16(acc[0][1], a0, q0[1], q0[3]);
        mma_bf16(acc[0][2], a0, q1[0], q1[2]);
        mma_bf16(acc[0][3], a0, q1[1], q1[3]);
        mma_bf16(acc[1][0], a1, q0[0], q0[2]);
        mma_bf16(acc[1][1], a1, q0[1], q0[3]);
        mma_bf16(acc[1][2], a1, q1[0], q1[2]);
        mma_bf16(acc[1][3], a1, q1[1], q1[3]);
    }

    // ---- epilogue: d regs -> Y (float2 stores) ----
    int r = row0 + wm * 32 + (lane >> 2);
    int c = col0 + wn * 32 + (lane & 3) * 2;
    #pragma unroll
    for (int i = 0; i < 2; i++) {
        #pragma unroll
        for (int j = 0; j < 4; j++) {
            float2 v0 = make_float2(acc[i][j][0], acc[i][j][1]);
            float2 v1 = make_float2(acc[i][j][2], acc[i][j][3]);
            *(float2*)&Y[(size_t)(r + i * 16) * M + c + j * 8] = v0;
            *(float2*)&Y[(size_t)(r + i * 16 + 8) * M + c + j * 8] = v1;
        }
    }
}

// ---------------- aggregation ------------------------------------------------
__global__ void aggregate(const float* __restrict__ st, const int* __restrict__ rowptr,
                          const int* __restrict__ perm,
                          __nv_bfloat16* __restrict__ ph, __nv_bfloat16* __restrict__ pl) {
    int i = blockIdx.x;
    int c = threadIdx.x;
    int s0 = rowptr[i], s1 = rowptr[i + 1];
    float a0 = 0.f, a1 = 0.f, a2 = 0.f, a3 = 0.f;
    int e = s0;
    for (; e + 3 < s1; e += 4) {
        int p0 = perm[e], p1 = perm[e + 1], p2 = perm[e + 2], p3 = perm[e + 3];
        a0 += st[p0 * 128 + c];
        a1 += st[p1 * 128 + c];
        a2 += st[p2 * 128 + c];
        a3 += st[p3 * 128 + c];
    }
    for (; e < s1; e++) a0 += st[perm[e] * 128 + c];
    float s = (a0 + a1) + (a2 + a3);
    __nv_bfloat16 h = __float2bfloat16(s);
    ph[i * 128 + c] = h;
    pl[i * 128 + c] = __float2bfloat16(s - __bfloat162float(h));
}

// ---------------- GRU elementwise, float4 vectorized ------------------------
__global__ void gru_k(const float* __restrict__ gi, const float* __restrict__ gh,
                      const float* __restrict__ b_ih, const float* __restrict__ b_hh,
                      const float* __restrict__ h, float* __restrict__ out,
                      __nv_bfloat16* __restrict__ oh, __nv_bfloat16* __restrict__ ol,
                      int n4) {
    int idx = blockIdx.x * blockDim.x + threadIdx.x;
    if (idx >= n4) return;
    int i = idx >> 5;
    int c4 = (idx & 31) * 4;
    const float4* gir = (const float4*)(gi + (size_t)i * 384 + c4);
    const float4* ghr = (const float4*)(gh + (size_t)i * 384 + c4);
    float4 ir = gir[0],  iz = gir[32],  in_ = gir[64];
    float4 hr = ghr[0],  hz = ghr[32],  hn = ghr[64];
    float4 bir = *(const float4*)(b_ih + c4);
    float4 biz = *(const float4*)(b_ih + 128 + c4);
    float4 bin = *(const float4*)(b_ih + 256 + c4);
    float4 bhr = *(const float4*)(b_hh + c4);
    float4 bhz = *(const float4*)(b_hh + 128 + c4);
    float4 bhn = *(const float4*)(b_hh + 256 + c4);
    float4 hv = *(const float4*)(h + (size_t)i * 128 + c4);

    float o[4], ohh[4], oll[4];
    #pragma unroll
    for (int q = 0; q < 4; q++) {
        float irq = ((&ir.x)[q] + (&bir.x)[q]) + ((&hr.x)[q] + (&bhr.x)[q]);
        float izq = ((&iz.x)[q] + (&biz.x)[q]) + ((&hz.x)[q] + (&bhz.x)[q]);
        float inq = (&in_.x)[q] + (&bin.x)[q];
        float hnq = (&hn.x)[q] + (&bhn.x)[q];
        float r = 1.f / (1.f + expf(-irq));
        float z = 1.f / (1.f + expf(-izq));
        float nval = tanhf(inq + r * hnq);
        float val = (1.f - z) * nval + z * (&hv.x)[q];
        o[q] = val;
        __nv_bfloat16 vh = __float2bfloat16(val);
        ohh[q] = __bfloat162float(vh);
        oll[q] = val - ohh[q];
    }
    *(float4*)(out + (size_t)i * 128 + c4) = make_float4(o[0], o[1], o[2], o[3]);
    __nv_bfloat162* ohp = (__nv_bfloat162*)(oh + (size_t)i * 128 + c4);
    __nv_bfloat162* olp = (__nv_bfloat162*)(ol + (size_t)i * 128 + c4);
    ohp[0] = __nv_bfloat162(__float2bfloat16(ohh[0]), __float2bfloat16(ohh[1]));
    ohp[1] = __nv_bfloat162(__float2bfloat16(ohh[2]), __float2bfloat16(ohh[3]));
    olp[0] = __nv_bfloat162(__float2bfloat16(oll[0]), __float2bfloat16(oll[1]));
    olp[1] = __nv_bfloat162(__float2bfloat16(oll[2]), __float2bfloat16(oll[3]));
}

// ---------------- launcher --------------------------------------------------
extern "C" void kernel_launch(void* const* d_in, const int* in_sizes, int n_in,
                              void* d_out, int out_size) {
    const float* x     = (const float*)d_in[0];
    const int*   ei    = (const int*)d_in[1];
    const float* W_lin = (const float*)d_in[2];
    const float* W_ih  = (const float*)d_in[3];
    const float* W_hh  = (const float*)d_in[4];
    const float* b_ih  = (const float*)d_in[5];
    const float* b_hh  = (const float*)d_in[6];
    float* out = (float*)d_out;

    const int* src = ei;
    const int* dst = ei + EE;

    float *sA_, *sB_, *gi_, *gh_, *wc_;
    int *cnt_, *rp_, *perm_, *bsum_;
    __nv_bfloat16 *sxh_, *sxl_, *sph_, *spl_, *wch_, *wcl_, *whhh_, *whhl_;
    cudaGetSymbolAddress((void**)&sA_,   g_sA);
    cudaGetSymbolAddress((void**)&sB_,   g_sB);
    cudaGetSymbolAddress((void**)&gi_,   g_gi);
    cudaGetSymbolAddress((void**)&gh_,   g_gh);
    cudaGetSymbolAddress((void**)&wc_,   g_wcomb);
    cudaGetSymbolAddress((void**)&cnt_,  g_cnt);
    cudaGetSymbolAddress((void**)&rp_,   g_rowptr);
    cudaGetSymbolAddress((void**)&perm_, g_perm);
    cudaGetSymbolAddress((void**)&bsum_, g_bsum);
    cudaGetSymbolAddress((void**)&sxh_,  g_sxh);
    cudaGetSymbolAddress((void**)&sxl_,  g_sxl);
    cudaGetSymbolAddress((void**)&sph_,  g_sph);
    cudaGetSymbolAddress((void**)&spl_,  g_spl);
    cudaGetSymbolAddress((void**)&wch_,  g_wch);
    cudaGetSymbolAddress((void**)&wcl_,  g_wcl);
    cudaGetSymbolAddress((void**)&whhh_, g_whhh);
    cudaGetSymbolAddress((void**)&whhl_, g_whhl);

    cudaFuncSetAttribute(gemm_tc, cudaFuncAttributeMaxDynamicSharedMemorySize, GT_SMEM);

    const int NB_SCAN = (NN + 1023) / 1024;
    const int N4 = NN * CC / 4;
    const dim3 gg(RTILES, 6);                 // 128x64 tiles over [NPAD, 384]

    // launch order: gemm_tc at my #4 (ncu -s 5 -c 1 lands there)
    conv_split<<<(N4 + 255) / 256, 256>>>(x, sxh_, sxl_, N4);                          // 1
    conv_split<<<(384 * CC / 4 + 255) / 256, 256>>>(W_hh, whhh_, whhl_, 384 * CC / 4); // 2
    zero_pad_bf16<<<((NPAD - NN) * CC + 255) / 256, 256>>>(sxh_, sxl_, sph_, spl_);    // 3
    gemm_tc<<<gg, 256, GT_SMEM>>>(sxh_, sxl_, whhh_, whhl_, gh_, 384);                 // 4 (profiled)

    wcomb_k<<<384, 128>>>(W_ih, W_lin, wc_);
    conv_split<<<(384 * CC / 4 + 255) / 256, 256>>>(wc_, wch_, wcl_, 384 * CC / 4);

    // ---- build CSR ----
    zero_int <<<(NN + 255) / 256, 256>>>(cnt_, NN);
    count_k  <<<(EE + 255) / 256, 256>>>(dst, cnt_);
    scan_block<<<NB_SCAN, 1024>>>(cnt_, rp_, bsum_, NN);
    scan_sums <<<1, 1>>>(bsum_, NB_SCAN);
    add_off   <<<(NN + 255) / 256, 256>>>(rp_, bsum_, NN);
    zero_int  <<<(NN + 255) / 256, 256>>>(cnt_, NN);
    fill_k    <<<(EE + 255) / 256, 256>>>(src, dst, rp_, cnt_, perm_);

    // ---- 3 propagation steps ----
    const float* sin = x;
    for (int step = 0; step < 3; step++) {
        float* sout = (step == 2) ? out : ((step == 0) ? sA_ : sB_);

        if (step > 0)   // step 0's gh computed at launch 4
            gemm_tc<<<gg, 256, GT_SMEM>>>(sxh_, sxl_, whhh_, whhl_, gh_, 384);
        aggregate<<<NN, 128>>>(sin, rp_, perm_, sph_, spl_);
        gemm_tc<<<gg, 256, GT_SMEM>>>(sph_, spl_, wch_, wcl_, gi_, 384);
        gru_k<<<(N4 + 255) / 256, 256>>>(gi_, gh_, b_ih, b_hh, sin, sout,
                                         sxh_, sxl_, N4);
        sin = sout;
    }
}